// round 17
// baseline (speedup 1.0000x reference)
#include <cuda_runtime.h>
#include <math.h>

// Problem dims (fixed)
#define TT 512
#define BB 32
#define II 1024
#define HH 1024
#define GG 4096
#define KK 1024

#define PM (TT*BB)
#define PN GG
#define PK 1024

#define NB 128             // persistent blocks (<=148 SMs, all co-resident)
#define NT 256

// recurrent smem: R parked [k][gr] (32 gr per block) + 8 per-warp reduce regions
#define SR_FLOATS (1024*32)        // 128 KB
#define SHW_FLOATS 1056            // 32 gr x 33 pitch
#define DYN_SMEM_BYTES ((SR_FLOATS + 8*SHW_FLOATS) * 4)   // 164,864 B

typedef unsigned long long ull;

// ---------------- scratch (device globals; no allocation) ----------------
__device__ float g_xg[TT*BB*GG];
__device__ float g_out0[TT*BB*HH];
__device__ float g_ht[2][2][HH*BB];     // TRANSPOSED h: [layer][buf][j*32 + b]
__device__ float g_c[2][BB*HH];         // [layer][b*H + j]

__device__ unsigned g_count = 0;
__device__ volatile unsigned g_sense_v = 0;

__device__ __forceinline__ float sigm(float x) { return 1.0f / (1.0f + expf(-x)); }

__device__ __forceinline__ ull pk2(float lo, float hi) {
    ull r; asm("mov.b64 %0, {%1,%2};" : "=l"(r) : "f"(lo), "f"(hi)); return r;
}
__device__ __forceinline__ void fma2(ull& d, ull a, ull b) {
    asm("fma.rn.f32x2 %0, %1, %2, %0;" : "+l"(d) : "l"(a), "l"(b));
}
__device__ __forceinline__ float2 upk2(ull v) {
    float2 r; asm("mov.b64 {%0,%1}, %2;" : "=f"(r.x), "=f"(r.y) : "l"(v)); return r;
}
__device__ __forceinline__ float ldcg(const float* p) {
    float v; asm volatile("ld.global.cg.f32 %0, [%1];" : "=f"(v) : "l"(p)); return v;
}

// sense-reversing grid barrier (validated R6/R7/R8)
__device__ __forceinline__ void gbar(unsigned* sense) {
    __syncthreads();
    if (threadIdx.x == 0) {
        unsigned s = 1u - *sense;
        *sense = s;
        __threadfence();
        if (atomicAdd(&g_count, 1u) == NB - 1u) {
            g_count = 0;
            __threadfence();
            g_sense_v = s;
        } else {
            while (g_sense_v != s) { }
        }
    }
    __syncthreads();
}

// ---------------- init: h into transposed layout, c as-is ----------------
__global__ void init_state(const float* __restrict__ h0, const float* __restrict__ c0) {
    int i = blockIdx.x * 256 + threadIdx.x;   // 0..65535
    if (i < 2*BB*HH) {
        int l = i >> 15, r = i & (BB*HH - 1);
        int b = r >> 10, j = r & (HH - 1);
        g_ht[l][0][j * BB + b] = h0[i];
        g_c[l][r] = c0[i];
    }
}

// ---------------- projection GEMM (validated R7/R8) ----------------
__global__ __launch_bounds__(256, 2) void proj_gemm(const float* __restrict__ A,
                                                    const float* __restrict__ W,
                                                    const float* __restrict__ bias,
                                                    float* __restrict__ C) {
    __shared__ __align__(16) float As[8][128];
    __shared__ __align__(16) float Bs[8][128];

    const int tid  = threadIdx.x;
    const int m0   = blockIdx.y * 128;
    const int n0   = blockIdx.x * 128;
    const int lRow = tid >> 1;
    const int lCol = (tid & 1) * 4;
    const int mr   = tid >> 4;
    const int nc   = tid & 15;

    const float* Aptr = A + (size_t)(m0 + lRow) * PK + lCol;
    const float* Wptr = W + (size_t)(n0 + lRow) * PK + lCol;

    ull acc2[8][4];
    #pragma unroll
    for (int i = 0; i < 8; i++)
        #pragma unroll
        for (int j = 0; j < 4; j++) acc2[i][j] = 0ull;

    float4 a = *(const float4*)(Aptr);
    float4 b = *(const float4*)(Wptr);

    for (int k0 = 0; k0 < PK; k0 += 8) {
        __syncthreads();
        As[lCol+0][lRow] = a.x; As[lCol+1][lRow] = a.y;
        As[lCol+2][lRow] = a.z; As[lCol+3][lRow] = a.w;
        Bs[lCol+0][lRow] = b.x; Bs[lCol+1][lRow] = b.y;
        Bs[lCol+2][lRow] = b.z; Bs[lCol+3][lRow] = b.w;
        __syncthreads();
        if (k0 + 8 < PK) {
            a = *(const float4*)(Aptr + k0 + 8);
            b = *(const float4*)(Wptr + k0 + 8);
        }
        #pragma unroll
        for (int k = 0; k < 8; k++) {
            float4 m1 = *(const float4*)&As[k][4*mr];
            float4 m2 = *(const float4*)&As[k][64 + 4*mr];
            ulonglong2 n1 = *(const ulonglong2*)&Bs[k][4*nc];
            ulonglong2 n2 = *(const ulonglong2*)&Bs[k][64 + 4*nc];
            ull rn[4] = {n1.x, n1.y, n2.x, n2.y};
            float rm[8] = {m1.x, m1.y, m1.z, m1.w, m2.x, m2.y, m2.z, m2.w};
            #pragma unroll
            for (int i = 0; i < 8; i++) {
                ull pm = pk2(rm[i], rm[i]);
                #pragma unroll
                for (int j = 0; j < 4; j++)
                    fma2(acc2[i][j], pm, rn[j]);
            }
        }
    }

    #pragma unroll
    for (int i = 0; i < 8; i++) {
        int mrow = m0 + ((i < 4) ? (4*mr + i) : (64 + 4*mr + i - 4));
        float* Crow = C + (size_t)mrow * PN + n0;
        float2 v0 = upk2(acc2[i][0]);
        float2 v1 = upk2(acc2[i][1]);
        float2 v2 = upk2(acc2[i][2]);
        float2 v3 = upk2(acc2[i][3]);
        int nq1 = 4*nc, nq2 = 64 + 4*nc;
        Crow[nq1+0] = v0.x + bias[n0+nq1+0];
        Crow[nq1+1] = v0.y + bias[n0+nq1+1];
        Crow[nq1+2] = v1.x + bias[n0+nq1+2];
        Crow[nq1+3] = v1.y + bias[n0+nq1+3];
        Crow[nq2+0] = v2.x + bias[n0+nq2+0];
        Crow[nq2+1] = v2.y + bias[n0+nq2+1];
        Crow[nq2+2] = v3.x + bias[n0+nq2+2];
        Crow[nq2+3] = v3.y + bias[n0+nq2+3];
    }
}

// ---------------- persistent recurrence v4: lane=batch, broadcast-R ----------------
// Block bid owns 32 gate rows {q*H + j0+jj} (j0=bid*8), all 32 b, K=1024.
// Warp w: k-slice [w*128,+128). lane = b. acc = 32 gate rows (16 f32x2 pairs).
// R parked once in smem as sr[k*32 + gr]; compute reads are pure broadcasts.
// h in GLOBAL, TRANSPOSED ht[j][b] -> per-k one coalesced 128B LDG, no staging.
__global__ __launch_bounds__(NT) void recurrent_persistent(
    int layer, const float* __restrict__ R, const float* __restrict__ bh,
    const float* __restrict__ xg, float* __restrict__ out)
{
    extern __shared__ __align__(16) float dynsmem[];
    float* sr  = dynsmem;                    // [k*32 + gr], 1024 x 32
    float* shh = dynsmem + SR_FLOATS;        // 8 warps x 1056 (reduce)

    const int tid  = threadIdx.x;
    const int bid  = blockIdx.x;
    const int j0   = bid * 8;
    const int lane = tid & 31;               // = batch b
    const int w    = tid >> 5;

    float* sh_w = shh + w * SHW_FLOATS;

    // ---- park R: sr[k*32 + gr] = R[(q*H + j0+jj)][k], gr = q*8+jj ----
    // lane = gr; warp w parks its own k-slice. STS banks = lane -> conflict-free.
    {
        int q = lane >> 3, jj = lane & 7;
        const float* Rrow = R + (size_t)(q * HH + j0 + jj) * KK + w * 128;
        float* srw = sr + w * 128 * 32;
        for (int kk = 0; kk < 128; kk += 4) {
            float4 v = *(const float4*)(Rrow + kk);
            srw[(kk+0)*32 + lane] = v.x;
            srw[(kk+1)*32 + lane] = v.y;
            srw[(kk+2)*32 + lane] = v.z;
            srw[(kk+3)*32 + lane] = v.w;
        }
    }
    __syncthreads();

    const float* srw = sr + w * 128 * 32;    // this warp's k-slice of R

    // pointwise identity: thread owns (b=pb, j=j0+pjj)
    const int pb  = tid & 31;
    const int pjj = tid >> 5;
    const int pj  = j0 + pjj;
    float* cbuf = g_c[layer];
    float c_reg = cbuf[pb * HH + pj];

    float bhv[4];
    #pragma unroll
    for (int q = 0; q < 4; q++) bhv[q] = bh[q * HH + pj];
    const float* xg_base = xg + (size_t)pb * GG + pj;

    float* hb0 = g_ht[layer][0];
    float* hb1 = g_ht[layer][1];

    unsigned sense = g_sense_v;

    for (int t = 0; t < TT; ++t) {
        const float* hs = (t & 1) ? hb1 : hb0;   // read buffer (transposed [j][b])
        float*       hd = (t & 1) ? hb0 : hb1;   // write buffer

        // prefetch xg for this step (independent of h)
        const float* xg_t = xg_base + (size_t)t * BB * GG;
        float xgv[4];
        #pragma unroll
        for (int q = 0; q < 4; q++) xgv[q] = ldcg(xg_t + q * HH);

        ull acc2[16];
        #pragma unroll
        for (int p = 0; p < 16; p++) acc2[p] = 0ull;

        // h pipeline: 8-deep double-buffered coalesced LDGs (hs[k*32 + lane])
        const float* hsl = hs + (size_t)w * 128 * 32 + lane;
        float hbuf[2][8];
        #pragma unroll
        for (int i = 0; i < 8; ++i) hbuf[0][i] = ldcg(hsl + i * 32);

        #pragma unroll 2
        for (int c = 0; c < 16; ++c) {
            float*       ha = hbuf[c & 1];
            float*       hb = hbuf[(c + 1) & 1];
            if (c < 15) {
                #pragma unroll
                for (int i = 0; i < 8; ++i)
                    hb[i] = ldcg(hsl + ((c + 1) * 8 + i) * 32);
            }
            #pragma unroll
            for (int kk = 0; kk < 8; ++kk) {
                const float* rp = srw + (c * 8 + kk) * 32;   // 16B-aligned, broadcast
                ulonglong2 u0 = *(const ulonglong2*)(rp + 0);    // gr pairs (0,1),(2,3)
                ulonglong2 u1 = *(const ulonglong2*)(rp + 8);    // (8,9),(10,11)... wait
                ulonglong2 u2 = *(const ulonglong2*)(rp + 16);
                ulonglong2 u3 = *(const ulonglong2*)(rp + 24);
                ulonglong2 u0b = *(const ulonglong2*)(rp + 4);   // (4,5),(6,7)
                ulonglong2 u1b = *(const ulonglong2*)(rp + 12);
                ulonglong2 u2b = *(const ulonglong2*)(rp + 20);
                ulonglong2 u3b = *(const ulonglong2*)(rp + 28);
                ull h2 = pk2(ha[kk], ha[kk]);
                fma2(acc2[0],  h2, u0.x);  fma2(acc2[1],  h2, u0.y);
                fma2(acc2[2],  h2, u0b.x); fma2(acc2[3],  h2, u0b.y);
                fma2(acc2[4],  h2, u1.x);  fma2(acc2[5],  h2, u1.y);
                fma2(acc2[6],  h2, u1b.x); fma2(acc2[7],  h2, u1b.y);
                fma2(acc2[8],  h2, u2.x);  fma2(acc2[9],  h2, u2.y);
                fma2(acc2[10], h2, u2b.x); fma2(acc2[11], h2, u2b.y);
                fma2(acc2[12], h2, u3.x);  fma2(acc2[13], h2, u3.y);
                fma2(acc2[14], h2, u3b.x); fma2(acc2[15], h2, u3b.y);
            }
        }

        // ---- write warp partials: sh_w[gr*33 + b], conflict-free per gr ----
        #pragma unroll
        for (int p = 0; p < 16; ++p) {
            float2 v = upk2(acc2[p]);
            sh_w[(2*p)     * 33 + lane] = v.x;
            sh_w[(2*p + 1) * 33 + lane] = v.y;
        }
        __syncthreads();

        // ---- reduce over 8 warps + pointwise (block-local, unchanged) ----
        float pre[4];
        #pragma unroll
        for (int q = 0; q < 4; ++q) {
            int base = (q * 8 + pjj) * 33 + pb;
            float ssum = 0.0f;
            #pragma unroll
            for (int w2 = 0; w2 < 8; ++w2) ssum += shh[w2 * SHW_FLOATS + base];
            pre[q] = sigm(xgv[q] + bhv[q] + ssum);
        }
        c_reg = c_reg * pre[3] + pre[2] - pre[0];
        float hnew = sigm(c_reg) - pre[1];
        hd[pj * BB + pb] = hnew;                               // transposed, coalesced
        out[(size_t)t * BB * HH + pb * HH + pj] = hnew;        // standard layout
        gbar(&sense);   // h[t+1] published
    }

    cbuf[pb * HH + pj] = c_reg;
}

// ---------------- finalize: (hT, cT) stacked after main output ----------------
__global__ void finalize(float* __restrict__ out) {
    int i = blockIdx.x * 256 + threadIdx.x;   // 0..65535
    if (i < 2 * BB * HH) {
        int l = i >> 15, r = i & (BB*HH - 1);
        int b = r >> 10, j = r & (HH - 1);
        out[(size_t)TT * BB * HH + i] = g_ht[l][0][j * BB + b];   // t=512 even -> buf 0
        out[(size_t)TT * BB * HH + 2 * BB * HH + i] = g_c[l][r];
    }
}

// ---------------- launch: 6 graph nodes ----------------
extern "C" void kernel_launch(void* const* d_in, const int* in_sizes, int n_in,
                              void* d_out, int out_size) {
    const float* x   = (const float*)d_in[0];
    const float* h0  = (const float*)d_in[1];
    const float* c0  = (const float*)d_in[2];
    const float* W0  = (const float*)d_in[3];
    const float* R0  = (const float*)d_in[4];
    const float* bi0 = (const float*)d_in[5];
    const float* bh0 = (const float*)d_in[6];
    const float* W1  = (const float*)d_in[7];
    const float* R1  = (const float*)d_in[8];
    const float* bi1 = (const float*)d_in[9];
    const float* bh1 = (const float*)d_in[10];
    float* out = (float*)d_out;

    float *p_xg = nullptr, *p_out0 = nullptr;
    cudaGetSymbolAddress((void**)&p_xg, g_xg);
    cudaGetSymbolAddress((void**)&p_out0, g_out0);

    cudaFuncSetAttribute(recurrent_persistent,
                         cudaFuncAttributeMaxDynamicSharedMemorySize, DYN_SMEM_BYTES);

    dim3 projGrid(PN / 128, PM / 128);

    init_state<<<256, 256>>>(h0, c0);

    proj_gemm<<<projGrid, 256>>>(x, W0, bi0, p_xg);
    recurrent_persistent<<<NB, NT, DYN_SMEM_BYTES>>>(0, R0, bh0, p_xg, p_out0);

    proj_gemm<<<projGrid, 256>>>(p_out0, W1, bi1, p_xg);
    recurrent_persistent<<<NB, NT, DYN_SMEM_BYTES>>>(1, R1, bh1, p_xg, out);

    finalize<<<256, 256>>>(out);
}